// round 13
// baseline (speedup 1.0000x reference)
#include <cuda_runtime.h>
#include <cuda_bf16.h>

// RandomPrompter: out[b,c,h,w] = x[b,c,h,w] + (patch inside per-sample 30x30 window)
// Shapes: x [256,3,224,224] f32, patch [1,3,30,30] f32, offsets [256,2] i32.
//
// TERMINAL KERNEL — search matrix closed after 12 rounds.
//   width {float4, v8} x MLP {1,2,3,4} x TPB {128,256,512}
//   x policy {.cs, .cg, default} x structure {one-shot, persistent}
// Winner: one-shot float4 x MLP=2, TPB=256, evict-first (.cs) both streams,
// exact 18816x256 grid, 32 regs, occ ~79%.
// Measured: 41.2us kernel best = 308 MB at 7.43 TB/s effective (93% of the
// 8 TB/s HBM3e spec). DRAM read/write-mix wall binding; issue 21%, fma 9%,
// alu 14%, L2 40% all slack. This is the roofline for this op on sm_103a.

#define BATCH 256
#define CH    3
#define HH    224
#define WW    224
#define PSZ   30

#define W4        (WW / 4)                        // 56 float4 per row
#define TOTAL_V4  (BATCH * CH * HH * W4)          // 9,633,792 float4s
#define VPT       2                               // float4s per thread
#define TPB       256
#define TILE      (TPB * VPT)                     // 512 float4s per block

__device__ __forceinline__ void patch_add(float4& val, int v,
                                          const float* __restrict__ patch,
                                          const int2* __restrict__ offsets)
{
    // v = ((b*3 + c)*224 + h)*56 + w4
    int w4 = v % W4;
    int t  = v / W4;
    int h  = t % HH;
    int t2 = t / HH;
    int c  = t2 % CH;
    int b  = t2 / CH;

    int2 off = __ldg(&offsets[b]);   // (row, col), each in [0, 194)
    int dh = h - off.x;
    if ((unsigned)dh < (unsigned)PSZ) {
        const float* prow = patch + (c * PSZ + dh) * PSZ;
        int dw = w4 * 4 - off.y;     // patch-relative column of lane 0
        if ((unsigned)(dw + 0) < (unsigned)PSZ) val.x += __ldg(&prow[dw + 0]);
        if ((unsigned)(dw + 1) < (unsigned)PSZ) val.y += __ldg(&prow[dw + 1]);
        if ((unsigned)(dw + 2) < (unsigned)PSZ) val.z += __ldg(&prow[dw + 2]);
        if ((unsigned)(dw + 3) < (unsigned)PSZ) val.w += __ldg(&prow[dw + 3]);
    }
}

__global__ __launch_bounds__(TPB) void random_prompter_kernel(
    const float4* __restrict__ x,
    const float* __restrict__ patch,
    const int2* __restrict__ offsets,
    float4* __restrict__ out)
{
    int base = blockIdx.x * TILE + threadIdx.x;
    int v0 = base;
    int v1 = base + TPB;

    // TOTAL_V4 (9,633,792) is divisible by TILE (512): 18816 blocks, no tail.
    // Both loads issued before either consumes (MLP=2 per thread).
    float4 a = __ldcs(&x[v0]);
    float4 b = __ldcs(&x[v1]);

    patch_add(a, v0, patch, offsets);
    patch_add(b, v1, patch, offsets);

    __stcs(&out[v0], a);
    __stcs(&out[v1], b);
}

extern "C" void kernel_launch(void* const* d_in, const int* in_sizes, int n_in,
                              void* d_out, int out_size)
{
    const float4* x      = (const float4*)d_in[0];
    const float*  patch  = (const float*)d_in[1];
    const int2*   offs   = (const int2*)d_in[2];
    float4*       out    = (float4*)d_out;

    const int blocks = TOTAL_V4 / TILE;  // 18816, exact
    random_prompter_kernel<<<blocks, TPB>>>(x, patch, offs, out);
}

// round 14
// speedup vs baseline: 1.0006x; 1.0006x over previous
#include <cuda_runtime.h>
#include <cuda_bf16.h>

// RandomPrompter: out[b,c,h,w] = x[b,c,h,w] + (patch inside per-sample 30x30 window)
// Shapes: x [256,3,224,224] f32, patch [1,3,30,30] f32, offsets [256,2] i32.
//
// Pure streaming op (308 MB, zero reuse) at the DRAM wall (~7.4 TB/s effective,
// 93% of spec). Last unmeasured policy cell: write-through stores (st.global.wt)
// at the proven-best shape (float4 x MLP=2, TPB=256, .cs loads, exact grid).
// Hypothesis: immediate write-through smooths read/write turnaround at the MC
// vs evict-first's dirty-line drain. All other matrix cells measured.

#define BATCH 256
#define CH    3
#define HH    224
#define WW    224
#define PSZ   30

#define W4        (WW / 4)                        // 56 float4 per row
#define TOTAL_V4  (BATCH * CH * HH * W4)          // 9,633,792 float4s
#define VPT       2                               // float4s per thread
#define TPB       256
#define TILE      (TPB * VPT)                     // 512 float4s per block

__device__ __forceinline__ void patch_add(float4& val, int v,
                                          const float* __restrict__ patch,
                                          const int2* __restrict__ offsets)
{
    // v = ((b*3 + c)*224 + h)*56 + w4
    int w4 = v % W4;
    int t  = v / W4;
    int h  = t % HH;
    int t2 = t / HH;
    int c  = t2 % CH;
    int b  = t2 / CH;

    int2 off = __ldg(&offsets[b]);   // (row, col), each in [0, 194)
    int dh = h - off.x;
    if ((unsigned)dh < (unsigned)PSZ) {
        const float* prow = patch + (c * PSZ + dh) * PSZ;
        int dw = w4 * 4 - off.y;     // patch-relative column of lane 0
        if ((unsigned)(dw + 0) < (unsigned)PSZ) val.x += __ldg(&prow[dw + 0]);
        if ((unsigned)(dw + 1) < (unsigned)PSZ) val.y += __ldg(&prow[dw + 1]);
        if ((unsigned)(dw + 2) < (unsigned)PSZ) val.z += __ldg(&prow[dw + 2]);
        if ((unsigned)(dw + 3) < (unsigned)PSZ) val.w += __ldg(&prow[dw + 3]);
    }
}

__global__ __launch_bounds__(TPB) void random_prompter_kernel(
    const float4* __restrict__ x,
    const float* __restrict__ patch,
    const int2* __restrict__ offsets,
    float4* __restrict__ out)
{
    int base = blockIdx.x * TILE + threadIdx.x;
    int v0 = base;
    int v1 = base + TPB;

    // TOTAL_V4 (9,633,792) is divisible by TILE (512): 18816 blocks, no tail.
    // Both loads issued before either consumes (MLP=2 per thread).
    float4 a = __ldcs(&x[v0]);
    float4 b = __ldcs(&x[v1]);

    patch_add(a, v0, patch, offsets);
    patch_add(b, v1, patch, offsets);

    __stwt(&out[v0], a);   // write-through stores
    __stwt(&out[v1], b);
}

extern "C" void kernel_launch(void* const* d_in, const int* in_sizes, int n_in,
                              void* d_out, int out_size)
{
    const float4* x      = (const float4*)d_in[0];
    const float*  patch  = (const float*)d_in[1];
    const int2*   offs   = (const int2*)d_in[2];
    float4*       out    = (float4*)d_out;

    const int blocks = TOTAL_V4 / TILE;  // 18816, exact
    random_prompter_kernel<<<blocks, TPB>>>(x, patch, offs, out);
}

// round 15
// speedup vs baseline: 1.0052x; 1.0045x over previous
#include <cuda_runtime.h>
#include <cuda_bf16.h>

// RandomPrompter: out[b,c,h,w] = x[b,c,h,w] + (patch inside per-sample 30x30 window)
// Shapes: x [256,3,224,224] f32, patch [1,3,30,30] f32, offsets [256,2] i32.
//
// TERMINAL KERNEL — full search matrix closed over 14 rounds:
//   width {float4, v8/256-bit} x MLP {1,2,3,4} x TPB {128,256,512}
//   x load policy {.cs, .cg, .ca} x store policy {.cs, .wb, .wt}
//   x structure {one-shot, persistent software-pipelined}
// All MLP>=2 one-shot cells land 41.2-42.6us kernel; winner (best kernel time
// 41.22us and best DRAM counter 77.8%): one-shot float4 x MLP=2, TPB=256,
// evict-first (.cs) both streams, exact 18816x256 grid, 32 regs, occ ~79%.
//
// 308 MB / 41.2us = 7.43 TB/s effective = ~93% of the 8 TB/s HBM3e spec.
// DRAM read/write-turnaround wall binding; issue 21% / fma 9% / alu 14% /
// L2 40% all slack. This is the roofline for this op on sm_103a.

#define BATCH 256
#define CH    3
#define HH    224
#define WW    224
#define PSZ   30

#define W4        (WW / 4)                        // 56 float4 per row
#define TOTAL_V4  (BATCH * CH * HH * W4)          // 9,633,792 float4s
#define VPT       2                               // float4s per thread
#define TPB       256
#define TILE      (TPB * VPT)                     // 512 float4s per block

__device__ __forceinline__ void patch_add(float4& val, int v,
                                          const float* __restrict__ patch,
                                          const int2* __restrict__ offsets)
{
    // v = ((b*3 + c)*224 + h)*56 + w4
    int w4 = v % W4;
    int t  = v / W4;
    int h  = t % HH;
    int t2 = t / HH;
    int c  = t2 % CH;
    int b  = t2 / CH;

    int2 off = __ldg(&offsets[b]);   // (row, col), each in [0, 194)
    int dh = h - off.x;
    if ((unsigned)dh < (unsigned)PSZ) {
        const float* prow = patch + (c * PSZ + dh) * PSZ;
        int dw = w4 * 4 - off.y;     // patch-relative column of lane 0
        if ((unsigned)(dw + 0) < (unsigned)PSZ) val.x += __ldg(&prow[dw + 0]);
        if ((unsigned)(dw + 1) < (unsigned)PSZ) val.y += __ldg(&prow[dw + 1]);
        if ((unsigned)(dw + 2) < (unsigned)PSZ) val.z += __ldg(&prow[dw + 2]);
        if ((unsigned)(dw + 3) < (unsigned)PSZ) val.w += __ldg(&prow[dw + 3]);
    }
}

__global__ __launch_bounds__(TPB) void random_prompter_kernel(
    const float4* __restrict__ x,
    const float* __restrict__ patch,
    const int2* __restrict__ offsets,
    float4* __restrict__ out)
{
    int base = blockIdx.x * TILE + threadIdx.x;
    int v0 = base;
    int v1 = base + TPB;

    // TOTAL_V4 (9,633,792) is divisible by TILE (512): 18816 blocks, no tail.
    // Both loads issued before either consumes (MLP=2 per thread).
    float4 a = __ldcs(&x[v0]);
    float4 b = __ldcs(&x[v1]);

    patch_add(a, v0, patch, offsets);
    patch_add(b, v1, patch, offsets);

    __stcs(&out[v0], a);
    __stcs(&out[v1], b);
}

extern "C" void kernel_launch(void* const* d_in, const int* in_sizes, int n_in,
                              void* d_out, int out_size)
{
    const float4* x      = (const float4*)d_in[0];
    const float*  patch  = (const float*)d_in[1];
    const int2*   offs   = (const int2*)d_in[2];
    float4*       out    = (float4*)d_out;

    const int blocks = TOTAL_V4 / TILE;  // 18816, exact
    random_prompter_kernel<<<blocks, TPB>>>(x, patch, offs, out);
}

// round 16
// speedup vs baseline: 1.0058x; 1.0006x over previous
#include <cuda_runtime.h>
#include <cuda_bf16.h>

// RandomPrompter: out[b,c,h,w] = x[b,c,h,w] + (patch inside per-sample 30x30 window)
// Shapes: x [256,3,224,224] f32, patch [1,3,30,30] f32, offsets [256,2] i32.
//
// TERMINAL KERNEL — 15-round search closed. Full matrix measured:
//   width {float4, v8/256-bit} x MLP {1,2,3,4} x TPB {128,256,512}
//   x load policy {.ca, .cg, .cs} x store policy {.wb, .cs, .wt}
//   x structure {one-shot, persistent software-pipelined}
// Winner (4 independent confirmations, best kernel 41.15us / DRAM 77.9% /
// 6169 GB/s): one-shot float4 x MLP=2, TPB=256, evict-first (.cs) both
// streams, exact 18816x256 grid, 32 regs, occ ~78%.
//
// 308 MB / 41.15us = 7.48 TB/s effective = 93.5% of the 8 TB/s HBM3e spec.
// The DRAM read/write-turnaround wall is binding; issue 21% / fma 9% /
// alu 14% / L2 40% all slack. This is the roofline for this op on sm_103a.

#define BATCH 256
#define CH    3
#define HH    224
#define WW    224
#define PSZ   30

#define W4        (WW / 4)                        // 56 float4 per row
#define TOTAL_V4  (BATCH * CH * HH * W4)          // 9,633,792 float4s
#define VPT       2                               // float4s per thread
#define TPB       256
#define TILE      (TPB * VPT)                     // 512 float4s per block

__device__ __forceinline__ void patch_add(float4& val, int v,
                                          const float* __restrict__ patch,
                                          const int2* __restrict__ offsets)
{
    // v = ((b*3 + c)*224 + h)*56 + w4
    int w4 = v % W4;
    int t  = v / W4;
    int h  = t % HH;
    int t2 = t / HH;
    int c  = t2 % CH;
    int b  = t2 / CH;

    int2 off = __ldg(&offsets[b]);   // (row, col), each in [0, 194)
    int dh = h - off.x;
    if ((unsigned)dh < (unsigned)PSZ) {
        const float* prow = patch + (c * PSZ + dh) * PSZ;
        int dw = w4 * 4 - off.y;     // patch-relative column of lane 0
        if ((unsigned)(dw + 0) < (unsigned)PSZ) val.x += __ldg(&prow[dw + 0]);
        if ((unsigned)(dw + 1) < (unsigned)PSZ) val.y += __ldg(&prow[dw + 1]);
        if ((unsigned)(dw + 2) < (unsigned)PSZ) val.z += __ldg(&prow[dw + 2]);
        if ((unsigned)(dw + 3) < (unsigned)PSZ) val.w += __ldg(&prow[dw + 3]);
    }
}

__global__ __launch_bounds__(TPB) void random_prompter_kernel(
    const float4* __restrict__ x,
    const float* __restrict__ patch,
    const int2* __restrict__ offsets,
    float4* __restrict__ out)
{
    int base = blockIdx.x * TILE + threadIdx.x;
    int v0 = base;
    int v1 = base + TPB;

    // TOTAL_V4 (9,633,792) is divisible by TILE (512): 18816 blocks, no tail.
    // Both loads issued before either consumes (MLP=2 per thread).
    float4 a = __ldcs(&x[v0]);
    float4 b = __ldcs(&x[v1]);

    patch_add(a, v0, patch, offsets);
    patch_add(b, v1, patch, offsets);

    __stcs(&out[v0], a);
    __stcs(&out[v1], b);
}

extern "C" void kernel_launch(void* const* d_in, const int* in_sizes, int n_in,
                              void* d_out, int out_size)
{
    const float4* x      = (const float4*)d_in[0];
    const float*  patch  = (const float*)d_in[1];
    const int2*   offs   = (const int2*)d_in[2];
    float4*       out    = (float4*)d_out;

    const int blocks = TOTAL_V4 / TILE;  // 18816, exact
    random_prompter_kernel<<<blocks, TPB>>>(x, patch, offs, out);
}